// round 7
// baseline (speedup 1.0000x reference)
#include <cuda_runtime.h>
#include <cstdint>

#define NN 100000
#define EE 3200000
#define FF 10
#define HH 20
#define DP 32                 // padded row length (floats) = 128 B = 1 line
#define NBLK 148
#define NTHR 512
#define NT   (NBLK * NTHR)

// ---------------- device scratch (no allocation allowed) ----------------
__device__ __align__(256) float g_x[NN * DP];
__device__ __align__(256) float g_h1[NN * DP];
__device__ __align__(256) float g_h2[NN * DP];
__device__ __align__(256) float g_agg[NN * DP];
__device__ __align__(256) int   g_row_ptr[NN + 1];
__device__ __align__(256) int   g_cursor[NN];    // doubles as histogram
__device__ __align__(256) int   g_col[EE];
__device__ __align__(256) int   g_bsum[NBLK];
__device__ unsigned g_bar_count;
__device__ volatile unsigned g_bar_gen;

// ---------------- software grid barrier (all blocks co-resident) -------
__device__ __forceinline__ void grid_sync() {
    __syncthreads();
    if (threadIdx.x == 0) {
        __threadfence();
        unsigned gen = g_bar_gen;
        if (atomicAdd(&g_bar_count, 1u) == NBLK - 1) {
            g_bar_count = 0;
            __threadfence();
            g_bar_gen = gen + 1;
        } else {
            while (g_bar_gen == gen) __nanosleep(64);
        }
        __threadfence();
    }
    __syncthreads();
}

// ---------------- gather: WARP per node ---------------------------------
// Warp prefetches 32 col indices in one LDG, then 8 independent row loads:
// lanes split as (edge_slot = lane>>3) x (chunk = lane&7); each edge's row
// is one 128B line covered by its 8 lanes in a single wavefront.
template <int NCH>
__device__ void gather_phase(const float* __restrict__ hin,
                             float* __restrict__ agg, int n, int gtid) {
    const int lane = threadIdx.x & 31;
    const int e_slot = lane >> 3;
    const int sub = lane & 7;
    const bool ldact = sub < NCH;
    const int coff = sub * 4;
    const int warp_g = gtid >> 5;
    const int nwarps = NT / 32;

    for (int i = warp_g; i < n; i += nwarps) {
        int beg = g_row_ptr[i];
        int deg = g_row_ptr[i + 1] - beg;
        float ax = 0.0f, ay = 0.0f, az = 0.0f, aw = 0.0f;
        for (int j0 = 0; j0 < deg; j0 += 32) {
            int cj = 0;
            if (j0 + lane < deg) cj = g_col[beg + j0 + lane];
            #pragma unroll
            for (int it = 0; it < 8; it++) {
                int j = j0 + it * 4 + e_slot;
                int s = __shfl_sync(0xFFFFFFFFu, cj, it * 4 + e_slot);
                if (ldact && j < deg) {
                    float4 v = *(const float4*)(hin + (size_t)s * DP + coff);
                    ax += v.x; ay += v.y; az += v.z; aw += v.w;
                }
            }
        }
        // reduce over edge_slot (lane bits 3,4)
        #pragma unroll
        for (int off = 8; off <= 16; off <<= 1) {
            ax += __shfl_xor_sync(0xFFFFFFFFu, ax, off);
            ay += __shfl_xor_sync(0xFFFFFFFFu, ay, off);
            az += __shfl_xor_sync(0xFFFFFFFFu, az, off);
            aw += __shfl_xor_sync(0xFFFFFFFFu, aw, off);
        }
        if (lane < NCH)
            *(float4*)(agg + (size_t)i * DP + lane * 4) =
                make_float4(ax, ay, az, aw);
    }
}

// ---------------- transform: THREAD per node ----------------------------
// hout = relu(agg @ Wrel + b + hin @ Wroot); weights broadcast from smem.
template <int DIN>
__device__ void transform_phase(const float* __restrict__ hin,
                                const float* __restrict__ Wrel,
                                const float* __restrict__ b,
                                const float* __restrict__ Wroot,
                                float* __restrict__ hout, int n,
                                float* __restrict__ sW, int gtid) {
    constexpr int NCH = (DIN + 3) / 4;
    float* sWrel  = sW;
    float* sWroot = sW + DIN * HH;
    float* sb     = sW + 2 * DIN * HH;
    for (int i = threadIdx.x; i < DIN * HH; i += NTHR) {
        sWrel[i]  = Wrel[i];
        sWroot[i] = Wroot[i];
    }
    if (threadIdx.x < HH) sb[threadIdx.x] = b[threadIdx.x];
    __syncthreads();

    for (int i = gtid; i < n; i += NT) {
        float a[NCH * 4], r[NCH * 4];
        #pragma unroll
        for (int c = 0; c < NCH; c++) {
            float4 va = *(const float4*)(g_agg + (size_t)i * DP + 4 * c);
            float4 vr = *(const float4*)(hin   + (size_t)i * DP + 4 * c);
            a[4*c+0] = va.x; a[4*c+1] = va.y; a[4*c+2] = va.z; a[4*c+3] = va.w;
            r[4*c+0] = vr.x; r[4*c+1] = vr.y; r[4*c+2] = vr.z; r[4*c+3] = vr.w;
        }
        float acc[HH];
        #pragma unroll
        for (int j = 0; j < HH; j++) acc[j] = sb[j];
        #pragma unroll
        for (int k = 0; k < DIN; k++) {
            float av = a[k], rv = r[k];
            #pragma unroll
            for (int j = 0; j < HH; j++)
                acc[j] += av * sWrel[k * HH + j] + rv * sWroot[k * HH + j];
        }
        #pragma unroll
        for (int c = 0; c < HH / 4; c++) {
            float4 o;
            o.x = fmaxf(acc[4*c+0], 0.0f);
            o.y = fmaxf(acc[4*c+1], 0.0f);
            o.z = fmaxf(acc[4*c+2], 0.0f);
            o.w = fmaxf(acc[4*c+3], 0.0f);
            *(float4*)(hout + (size_t)i * DP + 4 * c) = o;
        }
    }
}

// ---------------- pool + readout fused: warp per graph ------------------
__device__ __forceinline__ int bidx(const void* p, int i, bool is64) {
    return is64 ? (int)((const long long*)p)[i] : ((const int*)p)[i];
}

__device__ void pool_readout_phase(const float* __restrict__ h,
                                   const void* __restrict__ batch, bool is64,
                                   const float* __restrict__ Wlin,
                                   const float* __restrict__ blin,
                                   float* __restrict__ out, int n, int ng,
                                   int gtid) {
    int w = gtid >> 5;
    int lane = threadIdx.x & 31;
    if (w >= ng) return;

    int lo = 0, hi = n;
    while (lo < hi) {
        int mid = (lo + hi) >> 1;
        if (bidx(batch, mid, is64) < w) lo = mid + 1; else hi = mid;
    }
    int start = lo;
    hi = n;
    while (lo < hi) {
        int mid = (lo + hi) >> 1;
        if (bidx(batch, mid, is64) <= w) lo = mid + 1; else hi = mid;
    }
    int cnt = lo - start;

    float mx = 0.0f, sm = 0.0f;   // relu >= 0: 0-init max matches reference
    if (lane < HH) {
        const float* p = h + (size_t)start * DP + lane;
        int i = 0;
        for (; i + 4 <= cnt; i += 4) {
            float v0 = p[(size_t)(i + 0) * DP];
            float v1 = p[(size_t)(i + 1) * DP];
            float v2 = p[(size_t)(i + 2) * DP];
            float v3 = p[(size_t)(i + 3) * DP];
            mx = fmaxf(mx, fmaxf(fmaxf(v0, v1), fmaxf(v2, v3)));
            sm += (v0 + v1) + (v2 + v3);
        }
        for (; i < cnt; i++) {
            float v = p[(size_t)i * DP];
            mx = fmaxf(mx, v);
            sm += v;
        }
    }
    float mean = sm / fmaxf((float)cnt, 1.0f);

    float c0 = 0.0f, c1 = 0.0f;
    if (lane < HH) {
        c0 = mx * Wlin[lane * 2 + 0] + mean * Wlin[(HH + lane) * 2 + 0];
        c1 = mx * Wlin[lane * 2 + 1] + mean * Wlin[(HH + lane) * 2 + 1];
    }
    #pragma unroll
    for (int off = 16; off > 0; off >>= 1) {
        c0 += __shfl_down_sync(0xFFFFFFFFu, c0, off);
        c1 += __shfl_down_sync(0xFFFFFFFFu, c1, off);
    }
    if (lane == 0) {
        out[w * 2 + 0] = c0 + blin[0];
        out[w * 2 + 1] = c1 + blin[1];
    }
}

// ---------------- the single fused persistent kernel --------------------
__global__ void __launch_bounds__(NTHR, 1)
fused_kernel(const float* __restrict__ x,
             const void* __restrict__ ei,
             const void* __restrict__ batch,
             const float* __restrict__ Wrel1, const float* __restrict__ b1,
             const float* __restrict__ Wroot1,
             const float* __restrict__ Wrel2, const float* __restrict__ b2,
             const float* __restrict__ Wroot2,
             const float* __restrict__ Wrel3, const float* __restrict__ b3,
             const float* __restrict__ Wroot3,
             const float* __restrict__ Wlin, const float* __restrict__ blin,
             float* __restrict__ out, int n, int nE, int ng) {
    __shared__ float sW[2 * HH * HH + HH];
    __shared__ int s_wsum[NTHR / 32];
    __shared__ int s_boff;
    int t = threadIdx.x;
    int gtid = blockIdx.x * NTHR + t;
    int lane = t & 31;
    int wid = t >> 5;

    // dtype detect: int64 ids have zero high words; P(FP) ~ 2^-4096.
    unsigned oddw = 0;
    if (t < 128) oddw = ((const unsigned*)ei)[2 * t + 1];
    bool is64 = (__syncthreads_or(oddw != 0u) == 0);

    // ---- phase 0: zero histogram + pad x into g_x ----
    for (int i = gtid; i < n; i += NT) g_cursor[i] = 0;
    for (int i = gtid; i < n * DP; i += NT) {
        int row = i / DP, col = i % DP;
        g_x[i] = (col < FF) ? x[row * FF + col] : 0.0f;
    }
    grid_sync();

    // ---- phase 1: in-degree histogram over dst ----
    if (is64) {
        const long long* e = (const long long*)ei;
        for (int k = gtid; k < nE; k += NT)
            atomicAdd(&g_cursor[(int)e[nE + k]], 1);
    } else {
        const int* e = (const int*)ei;
        for (int k = gtid; k < nE; k += NT)
            atomicAdd(&g_cursor[e[nE + k]], 1);
    }
    grid_sync();

    // ---- phase 2: per-block exclusive scan of chunk; block sums out ----
    int chunk = (n + NBLK - 1) / NBLK;          // 676 (<= 2*NTHR)
    int base = blockIdx.x * chunk;
    {
        int i0 = 2 * t, i1 = 2 * t + 1;
        int v0 = (i0 < chunk && base + i0 < n) ? g_cursor[base + i0] : 0;
        int v1 = (i1 < chunk && base + i1 < n) ? g_cursor[base + i1] : 0;
        int ts = v0 + v1;
        int sc = ts;
        #pragma unroll
        for (int off = 1; off < 32; off <<= 1) {
            int u = __shfl_up_sync(0xFFFFFFFFu, sc, off);
            if (lane >= off) sc += u;
        }
        if (lane == 31) s_wsum[wid] = sc;
        __syncthreads();
        if (wid == 0) {
            int ws = (lane < NTHR / 32) ? s_wsum[lane] : 0;
            int wsc = ws;
            #pragma unroll
            for (int off = 1; off < 32; off <<= 1) {
                int u = __shfl_up_sync(0xFFFFFFFFu, wsc, off);
                if (lane >= off) wsc += u;
            }
            if (lane < NTHR / 32) s_wsum[lane] = wsc - ws;
            if (lane == NTHR / 32 - 1) g_bsum[blockIdx.x] = wsc;
        }
        __syncthreads();
        int excl = s_wsum[wid] + (sc - ts);
        if (i0 < chunk && base + i0 < n) g_row_ptr[base + i0] = excl;
        if (i1 < chunk && base + i1 < n) g_row_ptr[base + i1] = excl + v0;
    }
    grid_sync();

    // ---- phase 3: parallel block-offset reduce; finalize row_ptr/cursor --
    {
        int v = (t < NBLK && t < (int)blockIdx.x) ? g_bsum[t] : 0;
        #pragma unroll
        for (int off = 16; off > 0; off >>= 1)
            v += __shfl_down_sync(0xFFFFFFFFu, v, off);
        if (lane == 0) s_wsum[wid] = v;
        __syncthreads();
        if (t == 0) {
            int s = 0;
            #pragma unroll
            for (int k = 0; k < NTHR / 32; k++) s += s_wsum[k];
            s_boff = s;
            if (blockIdx.x == 0) g_row_ptr[n] = nE;
        }
        __syncthreads();
        int boff = s_boff;
        for (int i = t; i < chunk; i += NTHR) {
            int gi = base + i;
            if (gi < n) {
                int vv = g_row_ptr[gi] + boff;
                g_row_ptr[gi] = vv;
                g_cursor[gi] = vv;
            }
        }
    }
    grid_sync();

    // ---- phase 4: fill col (CSR by dst, values = src) ----
    if (is64) {
        const long long* e = (const long long*)ei;
        for (int k = gtid; k < nE; k += NT) {
            int s = (int)e[k];
            int d = (int)e[nE + k];
            g_col[atomicAdd(&g_cursor[d], 1)] = s;
        }
    } else {
        const int* e = (const int*)ei;
        for (int k = gtid; k < nE; k += NT) {
            int s = e[k];
            int d = e[nE + k];
            g_col[atomicAdd(&g_cursor[d], 1)] = s;
        }
    }
    grid_sync();

    // ---- layer 1: F=10 -> H=20 ----
    gather_phase<3>(g_x, g_agg, n, gtid);
    grid_sync();
    transform_phase<FF>(g_x, Wrel1, b1, Wroot1, g_h1, n, sW, gtid);
    grid_sync();

    // ---- layer 2: H -> H ----
    gather_phase<5>(g_h1, g_agg, n, gtid);
    grid_sync();
    transform_phase<HH>(g_h1, Wrel2, b2, Wroot2, g_h2, n, sW, gtid);
    grid_sync();

    // ---- layer 3: H -> H ----
    gather_phase<5>(g_h2, g_agg, n, gtid);
    grid_sync();
    transform_phase<HH>(g_h2, Wrel3, b3, Wroot3, g_h1, n, sW, gtid);
    grid_sync();

    // ---- pool + readout ----
    pool_readout_phase(g_h1, batch, is64, Wlin, blin, out, n, ng, gtid);
}

// ---------------- launcher: ONE kernel launch ----------------------------
extern "C" void kernel_launch(void* const* d_in, const int* in_sizes, int n_in,
                              void* d_out, int out_size) {
    const float* x      = (const float*)d_in[0];
    const void*  ei     = d_in[1];
    const void*  batch  = d_in[2];
    const float* Wrel1  = (const float*)d_in[3];
    const float* b1     = (const float*)d_in[4];
    const float* Wroot1 = (const float*)d_in[5];
    const float* Wrel2  = (const float*)d_in[6];
    const float* b2     = (const float*)d_in[7];
    const float* Wroot2 = (const float*)d_in[8];
    const float* Wrel3  = (const float*)d_in[9];
    const float* b3     = (const float*)d_in[10];
    const float* Wroot3 = (const float*)d_in[11];
    const float* Wlin   = (const float*)d_in[12];
    const float* blin   = (const float*)d_in[13];

    const int n  = in_sizes[0] / FF;
    const int nE = in_sizes[1] / 2;
    const int ng = out_size / 2;

    fused_kernel<<<NBLK, NTHR>>>(x, ei, batch,
                                 Wrel1, b1, Wroot1,
                                 Wrel2, b2, Wroot2,
                                 Wrel3, b3, Wroot3,
                                 Wlin, blin, (float*)d_out, n, nE, ng);
}

// round 8
// speedup vs baseline: 1.0730x; 1.0730x over previous
#include <cuda_runtime.h>
#include <cstdint>

#define NN 100000
#define EE 3200000
#define FF 10
#define HH 20
#define XP 12                 // padded x row (48 B, float4-aligned)
#define NBLK 148
#define NTHR 1024
#define NT   (NBLK * NTHR)

// ---------------- device scratch (total ~42 MB; inputs +55 MB < L2) -----
__device__ __align__(256) float g_x[NN * XP];
__device__ __align__(256) float g_h1[NN * HH];
__device__ __align__(256) float g_h2[NN * HH];
__device__ __align__(256) float g_agg[NN * HH];
__device__ __align__(256) int   g_row_ptr[NN + 1];
__device__ __align__(256) int   g_cursor[NN];    // doubles as histogram
__device__ __align__(256) int   g_col[EE];
__device__ __align__(256) int   g_bsum[NBLK];
__device__ unsigned g_bar_count;
__device__ volatile unsigned g_bar_gen;

// ---------------- software grid barrier ---------------------------------
__device__ __forceinline__ void grid_sync() {
    __syncthreads();
    if (threadIdx.x == 0) {
        __threadfence();
        unsigned gen = g_bar_gen;
        if (atomicAdd(&g_bar_count, 1u) == NBLK - 1) {
            g_bar_count = 0;
            __threadfence();
            g_bar_gen = gen + 1;
        } else {
            while (g_bar_gen == gen) __nanosleep(64);
        }
        __threadfence();
    }
    __syncthreads();
}

// ---------------- gather: warp per node, (4 edges x 8 chunks) lanes -----
// DROW = input row stride (12 or 20). Warp prefetches 32 cols in one LDG,
// then 8 iterations of 4 independent row loads; lane sub<NCH covers one
// float4 chunk. agg row stride is always HH(20); FF writes 3 chunks.
template <int DROW>
__device__ void gather_phase(const float* __restrict__ hin, int n, int gtid) {
    constexpr int NCH = DROW / 4;                // 3 or 5
    const int lane = threadIdx.x & 31;
    const int e_slot = lane >> 3;
    const int sub = lane & 7;
    const bool ldact = sub < NCH;
    const int coff = sub * 4;
    const int warp_g = gtid >> 5;
    const int nwarps = NT / 32;

    for (int i = warp_g; i < n; i += nwarps) {
        int beg = g_row_ptr[i];
        int deg = g_row_ptr[i + 1] - beg;
        float ax = 0.0f, ay = 0.0f, az = 0.0f, aw = 0.0f;
        for (int j0 = 0; j0 < deg; j0 += 32) {
            int cj = 0;
            if (j0 + lane < deg) cj = g_col[beg + j0 + lane];
            #pragma unroll
            for (int it = 0; it < 8; it++) {
                int j = j0 + it * 4 + e_slot;
                int s = __shfl_sync(0xFFFFFFFFu, cj, it * 4 + e_slot);
                if (ldact && j < deg) {
                    float4 v = *(const float4*)(hin + (size_t)s * DROW + coff);
                    ax += v.x; ay += v.y; az += v.z; aw += v.w;
                }
            }
        }
        #pragma unroll
        for (int off = 8; off <= 16; off <<= 1) {
            ax += __shfl_xor_sync(0xFFFFFFFFu, ax, off);
            ay += __shfl_xor_sync(0xFFFFFFFFu, ay, off);
            az += __shfl_xor_sync(0xFFFFFFFFu, az, off);
            aw += __shfl_xor_sync(0xFFFFFFFFu, aw, off);
        }
        if (lane < NCH)
            *(float4*)(g_agg + (size_t)i * HH + lane * 4) =
                make_float4(ax, ay, az, aw);
    }
}

// ---------------- transform: thread per node (coalesced rows) -----------
// hout[i] = relu(agg[i] @ Wrel + b + hin[i] @ Wroot). Streams chunks to
// keep live registers ~35 (fits 64-reg cap at 1024 thr/blk).
template <int DIN, int DROW>
__device__ void transform_phase(const float* __restrict__ hin,
                                const float* __restrict__ Wrel,
                                const float* __restrict__ b,
                                const float* __restrict__ Wroot,
                                float* __restrict__ hout, int n,
                                float* __restrict__ sW, int gtid) {
    constexpr int NC = DROW / 4;
    float* sWrel  = sW;
    float* sWroot = sW + DIN * HH;
    float* sb     = sW + 2 * DIN * HH;
    for (int i = threadIdx.x; i < DIN * HH; i += NTHR) {
        sWrel[i]  = Wrel[i];
        sWroot[i] = Wroot[i];
    }
    if (threadIdx.x < HH) sb[threadIdx.x] = b[threadIdx.x];
    __syncthreads();

    for (int i = gtid; i < n; i += NT) {
        float acc[HH];
        #pragma unroll
        for (int j = 0; j < HH; j++) acc[j] = sb[j];
        #pragma unroll
        for (int c = 0; c < NC; c++) {
            float4 va = *(const float4*)(g_agg + (size_t)i * HH  + 4 * c);
            float4 vr = *(const float4*)(hin   + (size_t)i * DROW + 4 * c);
            float av[4] = {va.x, va.y, va.z, va.w};
            float rv[4] = {vr.x, vr.y, vr.z, vr.w};
            #pragma unroll
            for (int kk = 0; kk < 4; kk++) {
                int k = 4 * c + kk;
                if (k < DIN) {
                    #pragma unroll
                    for (int j = 0; j < HH; j++)
                        acc[j] += av[kk] * sWrel[k * HH + j]
                                + rv[kk] * sWroot[k * HH + j];
                }
            }
        }
        #pragma unroll
        for (int c = 0; c < HH / 4; c++) {
            float4 o;
            o.x = fmaxf(acc[4*c+0], 0.0f);
            o.y = fmaxf(acc[4*c+1], 0.0f);
            o.z = fmaxf(acc[4*c+2], 0.0f);
            o.w = fmaxf(acc[4*c+3], 0.0f);
            *(float4*)(hout + (size_t)i * HH + 4 * c) = o;
        }
    }
}

// ---------------- pool + readout: warp per graph -------------------------
__device__ __forceinline__ int bidx(const void* p, int i, bool is64) {
    return is64 ? (int)((const long long*)p)[i] : ((const int*)p)[i];
}

__device__ void pool_readout_phase(const float* __restrict__ h,
                                   const void* __restrict__ batch, bool is64,
                                   const float* __restrict__ Wlin,
                                   const float* __restrict__ blin,
                                   float* __restrict__ out, int n, int ng,
                                   int gtid) {
    int w = gtid >> 5;
    int lane = threadIdx.x & 31;
    if (w >= ng) return;

    int lo = 0, hi = n;
    while (lo < hi) {
        int mid = (lo + hi) >> 1;
        if (bidx(batch, mid, is64) < w) lo = mid + 1; else hi = mid;
    }
    int start = lo;
    hi = n;
    while (lo < hi) {
        int mid = (lo + hi) >> 1;
        if (bidx(batch, mid, is64) <= w) lo = mid + 1; else hi = mid;
    }
    int cnt = lo - start;

    float mx = 0.0f, sm = 0.0f;   // relu >= 0: 0-init max matches reference
    if (lane < HH) {
        const float* p = h + (size_t)start * HH + lane;
        int i = 0;
        for (; i + 4 <= cnt; i += 4) {
            float v0 = p[(size_t)(i + 0) * HH];
            float v1 = p[(size_t)(i + 1) * HH];
            float v2 = p[(size_t)(i + 2) * HH];
            float v3 = p[(size_t)(i + 3) * HH];
            mx = fmaxf(mx, fmaxf(fmaxf(v0, v1), fmaxf(v2, v3)));
            sm += (v0 + v1) + (v2 + v3);
        }
        for (; i < cnt; i++) {
            float v = p[(size_t)i * HH];
            mx = fmaxf(mx, v);
            sm += v;
        }
    }
    float mean = sm / fmaxf((float)cnt, 1.0f);

    float c0 = 0.0f, c1 = 0.0f;
    if (lane < HH) {
        c0 = mx * Wlin[lane * 2 + 0] + mean * Wlin[(HH + lane) * 2 + 0];
        c1 = mx * Wlin[lane * 2 + 1] + mean * Wlin[(HH + lane) * 2 + 1];
    }
    #pragma unroll
    for (int off = 16; off > 0; off >>= 1) {
        c0 += __shfl_down_sync(0xFFFFFFFFu, c0, off);
        c1 += __shfl_down_sync(0xFFFFFFFFu, c1, off);
    }
    if (lane == 0) {
        out[w * 2 + 0] = c0 + blin[0];
        out[w * 2 + 1] = c1 + blin[1];
    }
}

// ---------------- the single fused persistent kernel --------------------
__global__ void __launch_bounds__(NTHR, 1)
fused_kernel(const float* __restrict__ x,
             const void* __restrict__ ei,
             const void* __restrict__ batch,
             const float* __restrict__ Wrel1, const float* __restrict__ b1,
             const float* __restrict__ Wroot1,
             const float* __restrict__ Wrel2, const float* __restrict__ b2,
             const float* __restrict__ Wroot2,
             const float* __restrict__ Wrel3, const float* __restrict__ b3,
             const float* __restrict__ Wroot3,
             const float* __restrict__ Wlin, const float* __restrict__ blin,
             float* __restrict__ out, int n, int nE, int ng) {
    __shared__ float sW[2 * HH * HH + HH];
    __shared__ int s_wsum[NTHR / 32];
    __shared__ int s_boff;
    int t = threadIdx.x;
    int gtid = blockIdx.x * NTHR + t;
    int lane = t & 31;
    int wid = t >> 5;

    // dtype detect: int64 ids have zero high words; P(FP) ~ 2^-4096.
    unsigned oddw = 0;
    if (t < 128) oddw = ((const unsigned*)ei)[2 * t + 1];
    bool is64 = (__syncthreads_or(oddw != 0u) == 0);

    // ---- phase 0: zero histogram + pad x into g_x ----
    for (int i = gtid; i < n; i += NT) g_cursor[i] = 0;
    for (int i = gtid; i < n * XP; i += NT) {
        int row = i / XP, col = i % XP;
        g_x[i] = (col < FF) ? x[row * FF + col] : 0.0f;
    }
    grid_sync();

    // ---- phase 1: in-degree histogram over dst ----
    if (is64) {
        const long long* e = (const long long*)ei;
        for (int k = gtid; k < nE; k += NT)
            atomicAdd(&g_cursor[(int)e[nE + k]], 1);
    } else {
        const int* e = (const int*)ei;
        for (int k = gtid; k < nE; k += NT)
            atomicAdd(&g_cursor[e[nE + k]], 1);
    }
    grid_sync();

    // ---- phase 2: per-block exclusive scan of chunk; block sums out ----
    int chunk = (n + NBLK - 1) / NBLK;          // 676 (<= 2*NTHR)
    int base = blockIdx.x * chunk;
    {
        int i0 = 2 * t, i1 = 2 * t + 1;
        int v0 = (i0 < chunk && base + i0 < n) ? g_cursor[base + i0] : 0;
        int v1 = (i1 < chunk && base + i1 < n) ? g_cursor[base + i1] : 0;
        int ts = v0 + v1;
        int sc = ts;
        #pragma unroll
        for (int off = 1; off < 32; off <<= 1) {
            int u = __shfl_up_sync(0xFFFFFFFFu, sc, off);
            if (lane >= off) sc += u;
        }
        if (lane == 31) s_wsum[wid] = sc;
        __syncthreads();
        if (wid == 0) {
            int ws = (lane < NTHR / 32) ? s_wsum[lane] : 0;
            int wsc = ws;
            #pragma unroll
            for (int off = 1; off < 32; off <<= 1) {
                int u = __shfl_up_sync(0xFFFFFFFFu, wsc, off);
                if (lane >= off) wsc += u;
            }
            if (lane < NTHR / 32) s_wsum[lane] = wsc - ws;
            if (lane == NTHR / 32 - 1) g_bsum[blockIdx.x] = wsc;
        }
        __syncthreads();
        int excl = s_wsum[wid] + (sc - ts);
        if (i0 < chunk && base + i0 < n) g_row_ptr[base + i0] = excl;
        if (i1 < chunk && base + i1 < n) g_row_ptr[base + i1] = excl + v0;
    }
    grid_sync();

    // ---- phase 3: parallel block-offset reduce; finalize row_ptr/cursor --
    {
        int v = (t < NBLK && t < (int)blockIdx.x) ? g_bsum[t] : 0;
        #pragma unroll
        for (int off = 16; off > 0; off >>= 1)
            v += __shfl_down_sync(0xFFFFFFFFu, v, off);
        if (lane == 0) s_wsum[wid] = v;
        __syncthreads();
        if (t == 0) {
            int s = 0;
            #pragma unroll
            for (int k = 0; k < NTHR / 32; k++) s += s_wsum[k];
            s_boff = s;
            if (blockIdx.x == 0) g_row_ptr[n] = nE;
        }
        __syncthreads();
        int boff = s_boff;
        for (int i = t; i < chunk; i += NTHR) {
            int gi = base + i;
            if (gi < n) {
                int vv = g_row_ptr[gi] + boff;
                g_row_ptr[gi] = vv;
                g_cursor[gi] = vv;
            }
        }
    }
    grid_sync();

    // ---- phase 4: fill col (CSR by dst, values = src) ----
    if (is64) {
        const long long* e = (const long long*)ei;
        for (int k = gtid; k < nE; k += NT) {
            int s = (int)e[k];
            int d = (int)e[nE + k];
            g_col[atomicAdd(&g_cursor[d], 1)] = s;
        }
    } else {
        const int* e = (const int*)ei;
        for (int k = gtid; k < nE; k += NT) {
            int s = e[k];
            int d = e[nE + k];
            g_col[atomicAdd(&g_cursor[d], 1)] = s;
        }
    }
    grid_sync();

    // ---- layer 1: F=10 -> H=20 ----
    gather_phase<XP>(g_x, n, gtid);
    grid_sync();
    transform_phase<FF, XP>(g_x, Wrel1, b1, Wroot1, g_h1, n, sW, gtid);
    grid_sync();

    // ---- layer 2: H -> H ----
    gather_phase<HH>(g_h1, n, gtid);
    grid_sync();
    transform_phase<HH, HH>(g_h1, Wrel2, b2, Wroot2, g_h2, n, sW, gtid);
    grid_sync();

    // ---- layer 3: H -> H ----
    gather_phase<HH>(g_h2, n, gtid);
    grid_sync();
    transform_phase<HH, HH>(g_h2, Wrel3, b3, Wroot3, g_h1, n, sW, gtid);
    grid_sync();

    // ---- pool + readout ----
    pool_readout_phase(g_h1, batch, is64, Wlin, blin, out, n, ng, gtid);
}

// ---------------- launcher: ONE kernel launch ----------------------------
extern "C" void kernel_launch(void* const* d_in, const int* in_sizes, int n_in,
                              void* d_out, int out_size) {
    const float* x      = (const float*)d_in[0];
    const void*  ei     = d_in[1];
    const void*  batch  = d_in[2];
    const float* Wrel1  = (const float*)d_in[3];
    const float* b1     = (const float*)d_in[4];
    const float* Wroot1 = (const float*)d_in[5];
    const float* Wrel2  = (const float*)d_in[6];
    const float* b2     = (const float*)d_in[7];
    const float* Wroot2 = (const float*)d_in[8];
    const float* Wrel3  = (const float*)d_in[9];
    const float* b3     = (const float*)d_in[10];
    const float* Wroot3 = (const float*)d_in[11];
    const float* Wlin   = (const float*)d_in[12];
    const float* blin   = (const float*)d_in[13];

    const int n  = in_sizes[0] / FF;
    const int nE = in_sizes[1] / 2;
    const int ng = out_size / 2;

    fused_kernel<<<NBLK, NTHR>>>(x, ei, batch,
                                 Wrel1, b1, Wroot1,
                                 Wrel2, b2, Wroot2,
                                 Wrel3, b3, Wroot3,
                                 Wlin, blin, (float*)d_out, n, nE, ng);
}

// round 9
// speedup vs baseline: 1.6574x; 1.5446x over previous
#include <cuda_runtime.h>
#include <cstdint>

#define NN 100000
#define EE 3200000
#define FF 10
#define HH 20
#define NBLK 148
#define NTHR 1024
#define NT   (NBLK * NTHR)

// ---------------- device scratch (~30 MB; well inside L2 with inputs) ---
__device__ __align__(256) float g_h1[NN * HH];
__device__ __align__(256) float g_h2[NN * HH];
__device__ __align__(256) int   g_row_ptr[NN + 1];
__device__ __align__(256) int   g_cursor[NN];    // doubles as histogram
__device__ __align__(256) int   g_col[EE];
__device__ __align__(256) int   g_bsum[NBLK];
__device__ unsigned g_bar_count;
__device__ volatile unsigned g_bar_gen;

// ---------------- software grid barrier ---------------------------------
__device__ __forceinline__ void grid_sync() {
    __syncthreads();
    if (threadIdx.x == 0) {
        __threadfence();
        unsigned gen = g_bar_gen;
        if (atomicAdd(&g_bar_count, 1u) == NBLK - 1) {
            g_bar_count = 0;
            __threadfence();
            g_bar_gen = gen + 1;
        } else {
            while (g_bar_gen == gen) __nanosleep(64);
        }
        __threadfence();
    }
    __syncthreads();
}

// ---------------- fused layer: thread per node (R5 shape, 64-reg diet) --
// hout[i] = relu( (sum_{j->i} hin[j]) @ Wrel + b + hin[i] @ Wroot )
// DIN=10: rows 40B, float2 loads. DIN=20: rows 80B, float4 loads.
template <int DIN>
__device__ void layer_phase(const float* __restrict__ hin,
                            const float* __restrict__ Wrel,
                            const float* __restrict__ b,
                            const float* __restrict__ Wroot,
                            float* __restrict__ hout, int n,
                            float* __restrict__ sW, int gtid) {
    float* sWrel  = sW;
    float* sWroot = sW + DIN * HH;
    float* sb     = sW + 2 * DIN * HH;
    for (int i = threadIdx.x; i < DIN * HH; i += NTHR) {
        sWrel[i]  = Wrel[i];
        sWroot[i] = Wroot[i];
    }
    if (threadIdx.x < HH) sb[threadIdx.x] = b[threadIdx.x];
    __syncthreads();

    for (int i = gtid; i < n; i += NT) {
        int beg = g_row_ptr[i];
        int end = g_row_ptr[i + 1];
        float acc[DIN];
        #pragma unroll
        for (int k = 0; k < DIN; k++) acc[k] = 0.0f;

        int e = beg;
        // unroll x2: two independent col->row chains in flight
        for (; e + 2 <= end; e += 2) {
            int s0 = g_col[e], s1 = g_col[e + 1];
            if (DIN % 4 == 0) {
                const float4* r0 = (const float4*)(hin + (size_t)s0 * DIN);
                const float4* r1 = (const float4*)(hin + (size_t)s1 * DIN);
                #pragma unroll
                for (int q = 0; q < DIN / 4; q++) {
                    float4 v0 = r0[q], v1 = r1[q];
                    acc[4*q+0] += v0.x + v1.x;
                    acc[4*q+1] += v0.y + v1.y;
                    acc[4*q+2] += v0.z + v1.z;
                    acc[4*q+3] += v0.w + v1.w;
                }
            } else {
                const float2* r0 = (const float2*)(hin + (size_t)s0 * DIN);
                const float2* r1 = (const float2*)(hin + (size_t)s1 * DIN);
                #pragma unroll
                for (int q = 0; q < DIN / 2; q++) {
                    float2 v0 = r0[q], v1 = r1[q];
                    acc[2*q+0] += v0.x + v1.x;
                    acc[2*q+1] += v0.y + v1.y;
                }
            }
        }
        if (e < end) {
            int s = g_col[e];
            if (DIN % 4 == 0) {
                const float4* r = (const float4*)(hin + (size_t)s * DIN);
                #pragma unroll
                for (int q = 0; q < DIN / 4; q++) {
                    float4 v = r[q];
                    acc[4*q+0] += v.x; acc[4*q+1] += v.y;
                    acc[4*q+2] += v.z; acc[4*q+3] += v.w;
                }
            } else {
                const float2* r = (const float2*)(hin + (size_t)s * DIN);
                #pragma unroll
                for (int q = 0; q < DIN / 2; q++) {
                    float2 v = r[q];
                    acc[2*q+0] += v.x; acc[2*q+1] += v.y;
                }
            }
        }

        // transform in two halves of 10 outputs (bounds live regs ~45)
        const float* xr = hin + (size_t)i * DIN;
        float* op = hout + (size_t)i * HH;
        #pragma unroll
        for (int half = 0; half < 2; half++) {
            const int jo = 10 * half;
            float o[10];
            #pragma unroll
            for (int j = 0; j < 10; j++) o[j] = sb[jo + j];
            #pragma unroll
            for (int k = 0; k < DIN; k++) {
                float a = acc[k];
                const float* wr = &sWrel[k * HH + jo];
                #pragma unroll
                for (int j = 0; j < 10; j++) o[j] += a * wr[j];
            }
            #pragma unroll
            for (int k = 0; k < DIN; k++) {
                float r = xr[k];                  // L1-hot reload
                const float* wo = &sWroot[k * HH + jo];
                #pragma unroll
                for (int j = 0; j < 10; j++) o[j] += r * wo[j];
            }
            #pragma unroll
            for (int j = 0; j < 10; j += 2) {
                float2 v;
                v.x = fmaxf(o[j + 0], 0.0f);
                v.y = fmaxf(o[j + 1], 0.0f);
                *(float2*)(op + jo + j) = v;
            }
        }
    }
}

// ---------------- pool + readout: warp per graph -------------------------
__device__ __forceinline__ int bidx(const void* p, int i, bool is64) {
    return is64 ? (int)((const long long*)p)[i] : ((const int*)p)[i];
}

__device__ void pool_readout_phase(const float* __restrict__ h,
                                   const void* __restrict__ batch, bool is64,
                                   const float* __restrict__ Wlin,
                                   const float* __restrict__ blin,
                                   float* __restrict__ out, int n, int ng,
                                   int gtid) {
    int w = gtid >> 5;
    int lane = threadIdx.x & 31;
    if (w >= ng) return;

    int lo = 0, hi = n;
    while (lo < hi) {
        int mid = (lo + hi) >> 1;
        if (bidx(batch, mid, is64) < w) lo = mid + 1; else hi = mid;
    }
    int start = lo;
    hi = n;
    while (lo < hi) {
        int mid = (lo + hi) >> 1;
        if (bidx(batch, mid, is64) <= w) lo = mid + 1; else hi = mid;
    }
    int cnt = lo - start;

    float mx = 0.0f, sm = 0.0f;   // relu >= 0: 0-init max matches reference
    if (lane < HH) {
        const float* p = h + (size_t)start * HH + lane;
        int i = 0;
        for (; i + 4 <= cnt; i += 4) {
            float v0 = p[(size_t)(i + 0) * HH];
            float v1 = p[(size_t)(i + 1) * HH];
            float v2 = p[(size_t)(i + 2) * HH];
            float v3 = p[(size_t)(i + 3) * HH];
            mx = fmaxf(mx, fmaxf(fmaxf(v0, v1), fmaxf(v2, v3)));
            sm += (v0 + v1) + (v2 + v3);
        }
        for (; i < cnt; i++) {
            float v = p[(size_t)i * HH];
            mx = fmaxf(mx, v);
            sm += v;
        }
    }
    float mean = sm / fmaxf((float)cnt, 1.0f);

    float c0 = 0.0f, c1 = 0.0f;
    if (lane < HH) {
        c0 = mx * Wlin[lane * 2 + 0] + mean * Wlin[(HH + lane) * 2 + 0];
        c1 = mx * Wlin[lane * 2 + 1] + mean * Wlin[(HH + lane) * 2 + 1];
    }
    #pragma unroll
    for (int off = 16; off > 0; off >>= 1) {
        c0 += __shfl_down_sync(0xFFFFFFFFu, c0, off);
        c1 += __shfl_down_sync(0xFFFFFFFFu, c1, off);
    }
    if (lane == 0) {
        out[w * 2 + 0] = c0 + blin[0];
        out[w * 2 + 1] = c1 + blin[1];
    }
}

// ---------------- the single fused persistent kernel --------------------
__global__ void __launch_bounds__(NTHR, 1)
fused_kernel(const float* __restrict__ x,
             const void* __restrict__ ei,
             const void* __restrict__ batch,
             const float* __restrict__ Wrel1, const float* __restrict__ b1,
             const float* __restrict__ Wroot1,
             const float* __restrict__ Wrel2, const float* __restrict__ b2,
             const float* __restrict__ Wroot2,
             const float* __restrict__ Wrel3, const float* __restrict__ b3,
             const float* __restrict__ Wroot3,
             const float* __restrict__ Wlin, const float* __restrict__ blin,
             float* __restrict__ out, int n, int nE, int ng) {
    __shared__ float sW[2 * HH * HH + HH];
    __shared__ int s_wsum[NTHR / 32];
    __shared__ int s_boff;
    int t = threadIdx.x;
    int gtid = blockIdx.x * NTHR + t;
    int lane = t & 31;
    int wid = t >> 5;

    // dtype detect: int64 ids have zero high words; P(FP) ~ 2^-4096.
    unsigned oddw = 0;
    if (t < 128) oddw = ((const unsigned*)ei)[2 * t + 1];
    bool is64 = (__syncthreads_or(oddw != 0u) == 0);

    // ---- phase 0: zero histogram ----
    for (int i = gtid; i < n; i += NT) g_cursor[i] = 0;
    grid_sync();

    // ---- phase 1: in-degree histogram over dst ----
    if (is64) {
        const long long* e = (const long long*)ei;
        for (int k = gtid; k < nE; k += NT)
            atomicAdd(&g_cursor[(int)e[nE + k]], 1);
    } else {
        const int* e = (const int*)ei;
        for (int k = gtid; k < nE; k += NT)
            atomicAdd(&g_cursor[e[nE + k]], 1);
    }
    grid_sync();

    // ---- phase 2: per-block exclusive scan of chunk; block sums out ----
    int chunk = (n + NBLK - 1) / NBLK;          // 676 (<= 2*NTHR)
    int base = blockIdx.x * chunk;
    {
        int i0 = 2 * t, i1 = 2 * t + 1;
        int v0 = (i0 < chunk && base + i0 < n) ? g_cursor[base + i0] : 0;
        int v1 = (i1 < chunk && base + i1 < n) ? g_cursor[base + i1] : 0;
        int ts = v0 + v1;
        int sc = ts;
        #pragma unroll
        for (int off = 1; off < 32; off <<= 1) {
            int u = __shfl_up_sync(0xFFFFFFFFu, sc, off);
            if (lane >= off) sc += u;
        }
        if (lane == 31) s_wsum[wid] = sc;
        __syncthreads();
        if (wid == 0) {
            int ws = (lane < NTHR / 32) ? s_wsum[lane] : 0;
            int wsc = ws;
            #pragma unroll
            for (int off = 1; off < 32; off <<= 1) {
                int u = __shfl_up_sync(0xFFFFFFFFu, wsc, off);
                if (lane >= off) wsc += u;
            }
            if (lane < NTHR / 32) s_wsum[lane] = wsc - ws;
            if (lane == NTHR / 32 - 1) g_bsum[blockIdx.x] = wsc;
        }
        __syncthreads();
        int excl = s_wsum[wid] + (sc - ts);
        if (i0 < chunk && base + i0 < n) g_row_ptr[base + i0] = excl;
        if (i1 < chunk && base + i1 < n) g_row_ptr[base + i1] = excl + v0;
    }
    grid_sync();

    // ---- phase 3: parallel block-offset reduce; finalize row_ptr/cursor --
    {
        int v = (t < NBLK && t < (int)blockIdx.x) ? g_bsum[t] : 0;
        #pragma unroll
        for (int off = 16; off > 0; off >>= 1)
            v += __shfl_down_sync(0xFFFFFFFFu, v, off);
        if (lane == 0) s_wsum[wid] = v;
        __syncthreads();
        if (t == 0) {
            int s = 0;
            #pragma unroll
            for (int k = 0; k < NTHR / 32; k++) s += s_wsum[k];
            s_boff = s;
            if (blockIdx.x == 0) g_row_ptr[n] = nE;
        }
        __syncthreads();
        int boff = s_boff;
        for (int i = t; i < chunk; i += NTHR) {
            int gi = base + i;
            if (gi < n) {
                int vv = g_row_ptr[gi] + boff;
                g_row_ptr[gi] = vv;
                g_cursor[gi] = vv;
            }
        }
    }
    grid_sync();

    // ---- phase 4: fill col (CSR by dst, values = src) ----
    if (is64) {
        const long long* e = (const long long*)ei;
        for (int k = gtid; k < nE; k += NT) {
            int s = (int)e[k];
            int d = (int)e[nE + k];
            g_col[atomicAdd(&g_cursor[d], 1)] = s;
        }
    } else {
        const int* e = (const int*)ei;
        for (int k = gtid; k < nE; k += NT) {
            int s = e[k];
            int d = e[nE + k];
            g_col[atomicAdd(&g_cursor[d], 1)] = s;
        }
    }
    grid_sync();

    // ---- layers: fused gather + transform, thread per node ----
    layer_phase<FF>(x,    Wrel1, b1, Wroot1, g_h1, n, sW, gtid);
    grid_sync();
    layer_phase<HH>(g_h1, Wrel2, b2, Wroot2, g_h2, n, sW, gtid);
    grid_sync();
    layer_phase<HH>(g_h2, Wrel3, b3, Wroot3, g_h1, n, sW, gtid);
    grid_sync();

    // ---- pool + readout ----
    pool_readout_phase(g_h1, batch, is64, Wlin, blin, out, n, ng, gtid);
}

// ---------------- launcher: ONE kernel launch ----------------------------
extern "C" void kernel_launch(void* const* d_in, const int* in_sizes, int n_in,
                              void* d_out, int out_size) {
    const float* x      = (const float*)d_in[0];
    const void*  ei     = d_in[1];
    const void*  batch  = d_in[2];
    const float* Wrel1  = (const float*)d_in[3];
    const float* b1     = (const float*)d_in[4];
    const float* Wroot1 = (const float*)d_in[5];
    const float* Wrel2  = (const float*)d_in[6];
    const float* b2     = (const float*)d_in[7];
    const float* Wroot2 = (const float*)d_in[8];
    const float* Wrel3  = (const float*)d_in[9];
    const float* b3     = (const float*)d_in[10];
    const float* Wroot3 = (const float*)d_in[11];
    const float* Wlin   = (const float*)d_in[12];
    const float* blin   = (const float*)d_in[13];

    const int n  = in_sizes[0] / FF;
    const int nE = in_sizes[1] / 2;
    const int ng = out_size / 2;

    fused_kernel<<<NBLK, NTHR>>>(x, ei, batch,
                                 Wrel1, b1, Wroot1,
                                 Wrel2, b2, Wroot2,
                                 Wrel3, b3, Wroot3,
                                 Wlin, blin, (float*)d_out, n, nE, ng);
}

// round 11
// speedup vs baseline: 2.4494x; 1.4778x over previous
#include <cuda_runtime.h>
#include <cuda_fp16.h>
#include <cstdint>

#define NN 100000
#define EE 3200000
#define FF 10
#define HH 20
#define XH 16                 // padded half row for x: 16 halves = 32 B
#define HHP 24                // padded half row for h: 24 halves = 48 B
#define NBLK 148
#define NTHR 512
#define NT   (NBLK * NTHR)

// ---------------- device scratch ----------------------------------------
__device__ __align__(256) __half g_xh[NN * XH];
__device__ __align__(256) float  g_h1f[NN * HH];
__device__ __align__(256) __half g_h1h[NN * HHP];
__device__ __align__(256) float  g_h2f[NN * HH];
__device__ __align__(256) __half g_h2h[NN * HHP];
__device__ __align__(256) int    g_row_ptr[NN + 1];
__device__ __align__(256) int    g_cursor[NN];   // doubles as histogram
__device__ __align__(256) int    g_col[EE];
__device__ __align__(256) int    g_bsum[NBLK];
__device__ unsigned g_bar_count;
__device__ volatile unsigned g_bar_gen;

// ---------------- helpers ------------------------------------------------
__device__ __forceinline__ float2 up2(unsigned u) {
    __half2 h = *reinterpret_cast<__half2*>(&u);
    return __half22float2(h);
}
__device__ __forceinline__ unsigned pk2(float a, float b) {
    __half2 h = __floats2half2_rn(a, b);
    return *reinterpret_cast<unsigned*>(&h);
}

// ---------------- software grid barrier ---------------------------------
__device__ __forceinline__ void grid_sync() {
    __syncthreads();
    if (threadIdx.x == 0) {
        __threadfence();
        unsigned gen = g_bar_gen;
        if (atomicAdd(&g_bar_count, 1u) == NBLK - 1) {
            g_bar_count = 0;
            __threadfence();
            g_bar_gen = gen + 1;
        } else {
            while (g_bar_gen == gen) __nanosleep(64);
        }
        __threadfence();
    }
    __syncthreads();
}

// ---------------- fused layer: thread per node, fp16 gather --------------
// acc = sum over in-neighbors of half rows (HROW halves/row, DIN valid),
// then hout = relu(acc @ Wrel + b + hin_f @ Wroot)  (all fp32).
// Writes hout_f (fp32, stride HH) and optionally hout_h (half, stride HHP).
template <int DIN, int HROW, bool WRITE_H>
__device__ void layer_phase(const __half* __restrict__ hin_h,
                            const float* __restrict__ hin_f, int fstride,
                            const float* __restrict__ Wrel,
                            const float* __restrict__ b,
                            const float* __restrict__ Wroot,
                            float* __restrict__ hout_f,
                            __half* __restrict__ hout_h,
                            int n, float* __restrict__ sW, int gtid) {
    float* sWrel  = sW;
    float* sWroot = sW + DIN * HH;
    float* sb     = sW + 2 * DIN * HH;
    for (int i = threadIdx.x; i < DIN * HH; i += NTHR) {
        sWrel[i]  = Wrel[i];
        sWroot[i] = Wroot[i];
    }
    if (threadIdx.x < HH) sb[threadIdx.x] = b[threadIdx.x];
    __syncthreads();

    for (int i = gtid; i < n; i += NT) {
        int beg = g_row_ptr[i];
        int end = g_row_ptr[i + 1];
        float acc[DIN];
        #pragma unroll
        for (int k = 0; k < DIN; k++) acc[k] = 0.0f;

        if (DIN == 10) {
            // row = uint4 (halves 0-7) + uint (halves 8-9); unroll x4
            int e = beg;
            for (; e + 4 <= end; e += 4) {
                #pragma unroll
                for (int u = 0; u < 4; u++) {
                    int s = g_col[e + u];
                    const __half* r = hin_h + (size_t)s * HROW;
                    uint4 c0 = *(const uint4*)r;
                    unsigned c1 = *(const unsigned*)(r + 8);
                    float2 f;
                    f = up2(c0.x); acc[0] += f.x; acc[1] += f.y;
                    f = up2(c0.y); acc[2] += f.x; acc[3] += f.y;
                    f = up2(c0.z); acc[4] += f.x; acc[5] += f.y;
                    f = up2(c0.w); acc[6] += f.x; acc[7] += f.y;
                    f = up2(c1);   acc[8] += f.x; acc[9] += f.y;
                }
            }
            for (; e < end; e++) {
                int s = g_col[e];
                const __half* r = hin_h + (size_t)s * HROW;
                uint4 c0 = *(const uint4*)r;
                unsigned c1 = *(const unsigned*)(r + 8);
                float2 f;
                f = up2(c0.x); acc[0] += f.x; acc[1] += f.y;
                f = up2(c0.y); acc[2] += f.x; acc[3] += f.y;
                f = up2(c0.z); acc[4] += f.x; acc[5] += f.y;
                f = up2(c0.w); acc[6] += f.x; acc[7] += f.y;
                f = up2(c1);   acc[8] += f.x; acc[9] += f.y;
            }
        } else {
            // row = uint4 + uint4 + uint2 (20 halves); unroll x2
            int e = beg;
            for (; e + 2 <= end; e += 2) {
                #pragma unroll
                for (int u = 0; u < 2; u++) {
                    int s = g_col[e + u];
                    const __half* r = hin_h + (size_t)s * HROW;
                    uint4 c0 = *(const uint4*)r;
                    uint4 c1 = *(const uint4*)(r + 8);
                    uint2 c2 = *(const uint2*)(r + 16);
                    float2 f;
                    f = up2(c0.x); acc[0]  += f.x; acc[1]  += f.y;
                    f = up2(c0.y); acc[2]  += f.x; acc[3]  += f.y;
                    f = up2(c0.z); acc[4]  += f.x; acc[5]  += f.y;
                    f = up2(c0.w); acc[6]  += f.x; acc[7]  += f.y;
                    f = up2(c1.x); acc[8]  += f.x; acc[9]  += f.y;
                    f = up2(c1.y); acc[10] += f.x; acc[11] += f.y;
                    f = up2(c1.z); acc[12] += f.x; acc[13] += f.y;
                    f = up2(c1.w); acc[14] += f.x; acc[15] += f.y;
                    f = up2(c2.x); acc[16] += f.x; acc[17] += f.y;
                    f = up2(c2.y); acc[18] += f.x; acc[19] += f.y;
                }
            }
            for (; e < end; e++) {
                int s = g_col[e];
                const __half* r = hin_h + (size_t)s * HROW;
                uint4 c0 = *(const uint4*)r;
                uint4 c1 = *(const uint4*)(r + 8);
                uint2 c2 = *(const uint2*)(r + 16);
                float2 f;
                f = up2(c0.x); acc[0]  += f.x; acc[1]  += f.y;
                f = up2(c0.y); acc[2]  += f.x; acc[3]  += f.y;
                f = up2(c0.z); acc[4]  += f.x; acc[5]  += f.y;
                f = up2(c0.w); acc[6]  += f.x; acc[7]  += f.y;
                f = up2(c1.x); acc[8]  += f.x; acc[9]  += f.y;
                f = up2(c1.y); acc[10] += f.x; acc[11] += f.y;
                f = up2(c1.z); acc[12] += f.x; acc[13] += f.y;
                f = up2(c1.w); acc[14] += f.x; acc[15] += f.y;
                f = up2(c2.x); acc[16] += f.x; acc[17] += f.y;
                f = up2(c2.y); acc[18] += f.x; acc[19] += f.y;
            }
        }

        // transform (fp32): o = acc@Wrel + b + xr@Wroot, relu
        float o[HH];
        #pragma unroll
        for (int j = 0; j < HH; j++) o[j] = sb[j];
        #pragma unroll
        for (int k = 0; k < DIN; k++) {
            float a = acc[k];
            #pragma unroll
            for (int j = 0; j < HH; j++) o[j] += a * sWrel[k * HH + j];
        }
        const float* xr = hin_f + (size_t)i * fstride;
        #pragma unroll
        for (int k = 0; k < DIN; k++) {
            float r = xr[k];
            #pragma unroll
            for (int j = 0; j < HH; j++) o[j] += r * sWroot[k * HH + j];
        }
        #pragma unroll
        for (int j = 0; j < HH; j++) o[j] = fmaxf(o[j], 0.0f);

        float* opf = hout_f + (size_t)i * HH;
        #pragma unroll
        for (int j = 0; j < HH; j += 2)
            *(float2*)(opf + j) = make_float2(o[j], o[j + 1]);

        if (WRITE_H) {
            uint4 u0, u1, u2;
            u0.x = pk2(o[0],  o[1]);  u0.y = pk2(o[2],  o[3]);
            u0.z = pk2(o[4],  o[5]);  u0.w = pk2(o[6],  o[7]);
            u1.x = pk2(o[8],  o[9]);  u1.y = pk2(o[10], o[11]);
            u1.z = pk2(o[12], o[13]); u1.w = pk2(o[14], o[15]);
            u2.x = pk2(o[16], o[17]); u2.y = pk2(o[18], o[19]);
            u2.z = 0u; u2.w = 0u;     // zero padding halves 20-23
            __half* oph = hout_h + (size_t)i * HHP;
            *(uint4*)(oph)      = u0;
            *(uint4*)(oph + 8)  = u1;
            *(uint4*)(oph + 16) = u2;
        }
    }
}

// ---------------- pool + readout: warp per graph -------------------------
__device__ __forceinline__ int bidx(const void* p, int i, bool is64) {
    return is64 ? (int)((const long long*)p)[i] : ((const int*)p)[i];
}

__device__ void pool_readout_phase(const float* __restrict__ h,
                                   const void* __restrict__ batch, bool is64,
                                   const float* __restrict__ Wlin,
                                   const float* __restrict__ blin,
                                   float* __restrict__ out, int n, int ng,
                                   int gtid) {
    int w = gtid >> 5;
    int lane = threadIdx.x & 31;
    if (w >= ng) return;

    int lo = 0, hi = n;
    while (lo < hi) {
        int mid = (lo + hi) >> 1;
        if (bidx(batch, mid, is64) < w) lo = mid + 1; else hi = mid;
    }
    int start = lo;
    hi = n;
    while (lo < hi) {
        int mid = (lo + hi) >> 1;
        if (bidx(batch, mid, is64) <= w) lo = mid + 1; else hi = mid;
    }
    int cnt = lo - start;

    float mx = 0.0f, sm = 0.0f;   // relu >= 0: 0-init max matches reference
    if (lane < HH) {
        const float* p = h + (size_t)start * HH + lane;
        int i = 0;
        for (; i + 4 <= cnt; i += 4) {
            float v0 = p[(size_t)(i + 0) * HH];
            float v1 = p[(size_t)(i + 1) * HH];
            float v2 = p[(size_t)(i + 2) * HH];
            float v3 = p[(size_t)(i + 3) * HH];
            mx = fmaxf(mx, fmaxf(fmaxf(v0, v1), fmaxf(v2, v3)));
            sm += (v0 + v1) + (v2 + v3);
        }
        for (; i < cnt; i++) {
            float v = p[(size_t)i * HH];
            mx = fmaxf(mx, v);
            sm += v;
        }
    }
    float mean = sm / fmaxf((float)cnt, 1.0f);

    float c0 = 0.0f, c1 = 0.0f;
    if (lane < HH) {
        c0 = mx * Wlin[lane * 2 + 0] + mean * Wlin[(HH + lane) * 2 + 0];
        c1 = mx * Wlin[lane * 2 + 1] + mean * Wlin[(HH + lane) * 2 + 1];
    }
    #pragma unroll
    for (int off = 16; off > 0; off >>= 1) {
        c0 += __shfl_down_sync(0xFFFFFFFFu, c0, off);
        c1 += __shfl_down_sync(0xFFFFFFFFu, c1, off);
    }
    if (lane == 0) {
        out[w * 2 + 0] = c0 + blin[0];
        out[w * 2 + 1] = c1 + blin[1];
    }
}

// ---------------- the single fused persistent kernel --------------------
__global__ void __launch_bounds__(NTHR, 1)
fused_kernel(const float* __restrict__ x,
             const void* __restrict__ ei,
             const void* __restrict__ batch,
             const float* __restrict__ Wrel1, const float* __restrict__ b1,
             const float* __restrict__ Wroot1,
             const float* __restrict__ Wrel2, const float* __restrict__ b2,
             const float* __restrict__ Wroot2,
             const float* __restrict__ Wrel3, const float* __restrict__ b3,
             const float* __restrict__ Wroot3,
             const float* __restrict__ Wlin, const float* __restrict__ blin,
             float* __restrict__ out, int n, int nE, int ng) {
    __shared__ float sW[2 * HH * HH + HH];
    __shared__ int s_wsum[NTHR / 32];
    __shared__ int s_boff;
    int t = threadIdx.x;
    int gtid = blockIdx.x * NTHR + t;
    int lane = t & 31;
    int wid = t >> 5;

    // dtype detect: int64 ids have zero high words; P(FP) ~ 2^-4096.
    unsigned oddw = 0;
    if (t < 128) oddw = ((const unsigned*)ei)[2 * t + 1];
    bool is64 = (__syncthreads_or(oddw != 0u) == 0);

    // ---- phase 0: zero histogram + half-cast x into g_xh ----
    for (int i = gtid; i < n; i += NT) g_cursor[i] = 0;
    for (int i = gtid; i < n * XH; i += NT) {
        int row = i / XH, col = i % XH;
        g_xh[i] = (col < FF) ? __float2half(x[row * FF + col]) : __half(0.0f);
    }
    grid_sync();

    // ---- phase 1: in-degree histogram over dst ----
    if (is64) {
        const long long* e = (const long long*)ei;
        for (int k = gtid; k < nE; k += NT)
            atomicAdd(&g_cursor[(int)e[nE + k]], 1);
    } else {
        const int* e = (const int*)ei;
        for (int k = gtid; k < nE; k += NT)
            atomicAdd(&g_cursor[e[nE + k]], 1);
    }
    grid_sync();

    // ---- phase 2: per-block exclusive scan of chunk; block sums out ----
    int chunk = (n + NBLK - 1) / NBLK;          // 676 (<= 2*NTHR)
    int base = blockIdx.x * chunk;
    {
        int i0 = 2 * t, i1 = 2 * t + 1;
        int v0 = (i0 < chunk && base + i0 < n) ? g_cursor[base + i0] : 0;
        int v1 = (i1 < chunk && base + i1 < n) ? g_cursor[base + i1] : 0;
        int ts = v0 + v1;
        int sc = ts;
        #pragma unroll
        for (int off = 1; off < 32; off <<= 1) {
            int u = __shfl_up_sync(0xFFFFFFFFu, sc, off);
            if (lane >= off) sc += u;
        }
        if (lane == 31) s_wsum[wid] = sc;
        __syncthreads();
        if (wid == 0) {
            int ws = (lane < NTHR / 32) ? s_wsum[lane] : 0;
            int wsc = ws;
            #pragma unroll
            for (int off = 1; off < 32; off <<= 1) {
                int u = __shfl_up_sync(0xFFFFFFFFu, wsc, off);
                if (lane >= off) wsc += u;
            }
            if (lane < NTHR / 32) s_wsum[lane] = wsc - ws;
            if (lane == NTHR / 32 - 1) g_bsum[blockIdx.x] = wsc;
        }
        __syncthreads();
        int excl = s_wsum[wid] + (sc - ts);
        if (i0 < chunk && base + i0 < n) g_row_ptr[base + i0] = excl;
        if (i1 < chunk && base + i1 < n) g_row_ptr[base + i1] = excl + v0;
    }
    grid_sync();

    // ---- phase 3: parallel block-offset reduce; finalize row_ptr/cursor --
    {
        int v = (t < NBLK && t < (int)blockIdx.x) ? g_bsum[t] : 0;
        #pragma unroll
        for (int off = 16; off > 0; off >>= 1)
            v += __shfl_down_sync(0xFFFFFFFFu, v, off);
        if (lane == 0) s_wsum[wid] = v;
        __syncthreads();
        if (t == 0) {
            int s = 0;
            #pragma unroll
            for (int k = 0; k < NTHR / 32; k++) s += s_wsum[k];
            s_boff = s;
            if (blockIdx.x == 0) g_row_ptr[n] = nE;
        }
        __syncthreads();
        int boff = s_boff;
        for (int i = t; i < chunk; i += NTHR) {
            int gi = base + i;
            if (gi < n) {
                int vv = g_row_ptr[gi] + boff;
                g_row_ptr[gi] = vv;
                g_cursor[gi] = vv;
            }
        }
    }
    grid_sync();

    // ---- phase 4: fill col (CSR by dst, values = src) ----
    if (is64) {
        const long long* e = (const long long*)ei;
        for (int k = gtid; k < nE; k += NT) {
            int s = (int)e[k];
            int d = (int)e[nE + k];
            g_col[atomicAdd(&g_cursor[d], 1)] = s;
        }
    } else {
        const int* e = (const int*)ei;
        for (int k = gtid; k < nE; k += NT) {
            int s = e[k];
            int d = e[nE + k];
            g_col[atomicAdd(&g_cursor[d], 1)] = s;
        }
    }
    grid_sync();

    // ---- layers ----
    layer_phase<FF, XH, true>(g_xh, x, FF, Wrel1, b1, Wroot1,
                              g_h1f, g_h1h, n, sW, gtid);
    grid_sync();
    layer_phase<HH, HHP, true>(g_h1h, g_h1f, HH, Wrel2, b2, Wroot2,
                               g_h2f, g_h2h, n, sW, gtid);
    grid_sync();
    layer_phase<HH, HHP, false>(g_h2h, g_h2f, HH, Wrel3, b3, Wroot3,
                                g_h1f, (__half*)nullptr, n, sW, gtid);
    grid_sync();

    // ---- pool + readout ----
    pool_readout_phase(g_h1f, batch, is64, Wlin, blin, out, n, ng, gtid);
}

// ---------------- launcher: ONE kernel launch ----------------------------
extern "C" void kernel_launch(void* const* d_in, const int* in_sizes, int n_in,
                              void* d_out, int out_size) {
    const float* x      = (const float*)d_in[0];
    const void*  ei     = d_in[1];
    const void*  batch  = d_in[2];
    const float* Wrel1  = (const float*)d_in[3];
    const float* b1     = (const float*)d_in[4];
    const float* Wroot1 = (const float*)d_in[5];
    const float* Wrel2  = (const float*)d_in[6];
    const float* b2     = (const float*)d_in[7];
    const float* Wroot2 = (const float*)d_in[8];
    const float* Wrel3  = (const float*)d_in[9];
    const float* b3     = (const float*)d_in[10];
    const float* Wroot3 = (const float*)d_in[11];
    const float* Wlin   = (const float*)d_in[12];
    const float* blin   = (const float*)d_in[13];

    const int n  = in_sizes[0] / FF;
    const int nE = in_sizes[1] / 2;
    const int ng = out_size / 2;

    fused_kernel<<<NBLK, NTHR>>>(x, ei, batch,
                                 Wrel1, b1, Wroot1,
                                 Wrel2, b2, Wroot2,
                                 Wrel3, b3, Wroot3,
                                 Wlin, blin, (float*)d_out, n, nE, ng);
}

// round 12
// speedup vs baseline: 2.4622x; 1.0052x over previous
#include <cuda_runtime.h>
#include <cuda_fp16.h>
#include <cstdint>

#define NN 100000
#define EE 3200000
#define FF 10
#define HH 20
#define XH 16                 // padded half row for x: 16 halves = 32 B
#define HHP 24                // padded half row for h: 24 halves = 48 B
#define NBLK 148
#define NTHR 512
#define NT   (NBLK * NTHR)

// ---------------- device scratch ----------------------------------------
__device__ __align__(256) __half g_xh[NN * XH];
__device__ __align__(256) float  g_h1f[NN * HH];
__device__ __align__(256) __half g_h1h[NN * HHP];
__device__ __align__(256) float  g_h2f[NN * HH];
__device__ __align__(256) __half g_h2h[NN * HHP];
__device__ __align__(256) int    g_row_ptr[NN + 1];
__device__ __align__(256) int    g_cursor[NN];   // doubles as histogram
__device__ __align__(256) int    g_col[EE];
__device__ __align__(256) int    g_bsum[NBLK];
__device__ unsigned g_bar_count;
__device__ volatile unsigned g_bar_gen;

// ---------------- helpers ------------------------------------------------
__device__ __forceinline__ float2 up2(unsigned u) {
    __half2 h = *reinterpret_cast<__half2*>(&u);
    return __half22float2(h);
}
__device__ __forceinline__ unsigned pk2(float a, float b) {
    __half2 h = __floats2half2_rn(a, b);
    return *reinterpret_cast<unsigned*>(&h);
}

// ---------------- software grid barrier ---------------------------------
__device__ __forceinline__ void grid_sync() {
    __syncthreads();
    if (threadIdx.x == 0) {
        __threadfence();
        unsigned gen = g_bar_gen;
        if (atomicAdd(&g_bar_count, 1u) == NBLK - 1) {
            g_bar_count = 0;
            __threadfence();
            g_bar_gen = gen + 1;
        } else {
            while (g_bar_gen == gen) __nanosleep(64);
        }
        __threadfence();
    }
    __syncthreads();
}

// ---------------- fused layer: thread per node, fp16 gather --------------
template <int DIN, int HROW, bool WRITE_H>
__device__ void layer_phase(const __half* __restrict__ hin_h,
                            const float* __restrict__ hin_f, int fstride,
                            const float* __restrict__ Wrel,
                            const float* __restrict__ b,
                            const float* __restrict__ Wroot,
                            float* __restrict__ hout_f,
                            __half* __restrict__ hout_h,
                            int n, float* __restrict__ sW, int gtid) {
    float* sWrel  = sW;
    float* sWroot = sW + DIN * HH;
    float* sb     = sW + 2 * DIN * HH;
    for (int i = threadIdx.x; i < DIN * HH; i += NTHR) {
        sWrel[i]  = Wrel[i];
        sWroot[i] = Wroot[i];
    }
    if (threadIdx.x < HH) sb[threadIdx.x] = b[threadIdx.x];
    __syncthreads();

    for (int i = gtid; i < n; i += NT) {
        int beg = g_row_ptr[i];
        int end = g_row_ptr[i + 1];
        float acc[DIN];
        #pragma unroll
        for (int k = 0; k < DIN; k++) acc[k] = 0.0f;

        if (DIN == 10) {
            // row = uint4 + uint (2 loads/edge); unroll x8 -> 16 row loads
            int e = beg;
            for (; e + 8 <= end; e += 8) {
                uint4    c0[8];
                unsigned c1[8];
                #pragma unroll
                for (int u = 0; u < 8; u++) {
                    const __half* r = hin_h + (size_t)g_col[e + u] * HROW;
                    c0[u] = *(const uint4*)r;
                    c1[u] = *(const unsigned*)(r + 8);
                }
                #pragma unroll
                for (int u = 0; u < 8; u++) {
                    float2 f;
                    f = up2(c0[u].x); acc[0] += f.x; acc[1] += f.y;
                    f = up2(c0[u].y); acc[2] += f.x; acc[3] += f.y;
                    f = up2(c0[u].z); acc[4] += f.x; acc[5] += f.y;
                    f = up2(c0[u].w); acc[6] += f.x; acc[7] += f.y;
                    f = up2(c1[u]);   acc[8] += f.x; acc[9] += f.y;
                }
            }
            for (; e < end; e++) {
                const __half* r = hin_h + (size_t)g_col[e] * HROW;
                uint4 c0 = *(const uint4*)r;
                unsigned c1 = *(const unsigned*)(r + 8);
                float2 f;
                f = up2(c0.x); acc[0] += f.x; acc[1] += f.y;
                f = up2(c0.y); acc[2] += f.x; acc[3] += f.y;
                f = up2(c0.z); acc[4] += f.x; acc[5] += f.y;
                f = up2(c0.w); acc[6] += f.x; acc[7] += f.y;
                f = up2(c1);   acc[8] += f.x; acc[9] += f.y;
            }
        } else {
            // row = uint4+uint4+uint2 (3 loads/edge); unroll x4 -> 12 loads
            int e = beg;
            for (; e + 4 <= end; e += 4) {
                uint4 c0[4], c1[4];
                uint2 c2[4];
                #pragma unroll
                for (int u = 0; u < 4; u++) {
                    const __half* r = hin_h + (size_t)g_col[e + u] * HROW;
                    c0[u] = *(const uint4*)r;
                    c1[u] = *(const uint4*)(r + 8);
                    c2[u] = *(const uint2*)(r + 16);
                }
                #pragma unroll
                for (int u = 0; u < 4; u++) {
                    float2 f;
                    f = up2(c0[u].x); acc[0]  += f.x; acc[1]  += f.y;
                    f = up2(c0[u].y); acc[2]  += f.x; acc[3]  += f.y;
                    f = up2(c0[u].z); acc[4]  += f.x; acc[5]  += f.y;
                    f = up2(c0[u].w); acc[6]  += f.x; acc[7]  += f.y;
                    f = up2(c1[u].x); acc[8]  += f.x; acc[9]  += f.y;
                    f = up2(c1[u].y); acc[10] += f.x; acc[11] += f.y;
                    f = up2(c1[u].z); acc[12] += f.x; acc[13] += f.y;
                    f = up2(c1[u].w); acc[14] += f.x; acc[15] += f.y;
                    f = up2(c2[u].x); acc[16] += f.x; acc[17] += f.y;
                    f = up2(c2[u].y); acc[18] += f.x; acc[19] += f.y;
                }
            }
            for (; e < end; e++) {
                const __half* r = hin_h + (size_t)g_col[e] * HROW;
                uint4 c0 = *(const uint4*)r;
                uint4 c1 = *(const uint4*)(r + 8);
                uint2 c2 = *(const uint2*)(r + 16);
                float2 f;
                f = up2(c0.x); acc[0]  += f.x; acc[1]  += f.y;
                f = up2(c0.y); acc[2]  += f.x; acc[3]  += f.y;
                f = up2(c0.z); acc[4]  += f.x; acc[5]  += f.y;
                f = up2(c0.w); acc[6]  += f.x; acc[7]  += f.y;
                f = up2(c1.x); acc[8]  += f.x; acc[9]  += f.y;
                f = up2(c1.y); acc[10] += f.x; acc[11] += f.y;
                f = up2(c1.z); acc[12] += f.x; acc[13] += f.y;
                f = up2(c1.w); acc[14] += f.x; acc[15] += f.y;
                f = up2(c2.x); acc[16] += f.x; acc[17] += f.y;
                f = up2(c2.y); acc[18] += f.x; acc[19] += f.y;
            }
        }

        // transform (fp32): o = acc@Wrel + b + xr@Wroot, relu
        float o[HH];
        #pragma unroll
        for (int j = 0; j < HH; j++) o[j] = sb[j];
        #pragma unroll
        for (int k = 0; k < DIN; k++) {
            float a = acc[k];
            #pragma unroll
            for (int j = 0; j < HH; j++) o[j] += a * sWrel[k * HH + j];
        }
        const float* xr = hin_f + (size_t)i * fstride;
        #pragma unroll
        for (int k = 0; k < DIN; k++) {
            float r = xr[k];
            #pragma unroll
            for (int j = 0; j < HH; j++) o[j] += r * sWroot[k * HH + j];
        }
        #pragma unroll
        for (int j = 0; j < HH; j++) o[j] = fmaxf(o[j], 0.0f);

        float* opf = hout_f + (size_t)i * HH;
        #pragma unroll
        for (int j = 0; j < HH; j += 2)
            *(float2*)(opf + j) = make_float2(o[j], o[j + 1]);

        if (WRITE_H) {
            uint4 u0, u1, u2;
            u0.x = pk2(o[0],  o[1]);  u0.y = pk2(o[2],  o[3]);
            u0.z = pk2(o[4],  o[5]);  u0.w = pk2(o[6],  o[7]);
            u1.x = pk2(o[8],  o[9]);  u1.y = pk2(o[10], o[11]);
            u1.z = pk2(o[12], o[13]); u1.w = pk2(o[14], o[15]);
            u2.x = pk2(o[16], o[17]); u2.y = pk2(o[18], o[19]);
            u2.z = 0u; u2.w = 0u;
            __half* oph = hout_h + (size_t)i * HHP;
            *(uint4*)(oph)      = u0;
            *(uint4*)(oph + 8)  = u1;
            *(uint4*)(oph + 16) = u2;
        }
    }
}

// ---------------- pool + readout: warp per graph -------------------------
__device__ __forceinline__ int bidx(const void* p, int i, bool is64) {
    return is64 ? (int)((const long long*)p)[i] : ((const int*)p)[i];
}

__device__ void pool_readout_phase(const float* __restrict__ h,
                                   const void* __restrict__ batch, bool is64,
                                   const float* __restrict__ Wlin,
                                   const float* __restrict__ blin,
                                   float* __restrict__ out, int n, int ng,
                                   int gtid) {
    int w = gtid >> 5;
    int lane = threadIdx.x & 31;
    if (w >= ng) return;

    int lo = 0, hi = n;
    while (lo < hi) {
        int mid = (lo + hi) >> 1;
        if (bidx(batch, mid, is64) < w) lo = mid + 1; else hi = mid;
    }
    int start = lo;
    hi = n;
    while (lo < hi) {
        int mid = (lo + hi) >> 1;
        if (bidx(batch, mid, is64) <= w) lo = mid + 1; else hi = mid;
    }
    int cnt = lo - start;

    float mx = 0.0f, sm = 0.0f;   // relu >= 0: 0-init max matches reference
    if (lane < HH) {
        const float* p = h + (size_t)start * HH + lane;
        int i = 0;
        for (; i + 4 <= cnt; i += 4) {
            float v0 = p[(size_t)(i + 0) * HH];
            float v1 = p[(size_t)(i + 1) * HH];
            float v2 = p[(size_t)(i + 2) * HH];
            float v3 = p[(size_t)(i + 3) * HH];
            mx = fmaxf(mx, fmaxf(fmaxf(v0, v1), fmaxf(v2, v3)));
            sm += (v0 + v1) + (v2 + v3);
        }
        for (; i < cnt; i++) {
            float v = p[(size_t)i * HH];
            mx = fmaxf(mx, v);
            sm += v;
        }
    }
    float mean = sm / fmaxf((float)cnt, 1.0f);

    float c0 = 0.0f, c1 = 0.0f;
    if (lane < HH) {
        c0 = mx * Wlin[lane * 2 + 0] + mean * Wlin[(HH + lane) * 2 + 0];
        c1 = mx * Wlin[lane * 2 + 1] + mean * Wlin[(HH + lane) * 2 + 1];
    }
    #pragma unroll
    for (int off = 16; off > 0; off >>= 1) {
        c0 += __shfl_down_sync(0xFFFFFFFFu, c0, off);
        c1 += __shfl_down_sync(0xFFFFFFFFu, c1, off);
    }
    if (lane == 0) {
        out[w * 2 + 0] = c0 + blin[0];
        out[w * 2 + 1] = c1 + blin[1];
    }
}

// ---------------- the single fused persistent kernel --------------------
__global__ void __launch_bounds__(NTHR, 1)
fused_kernel(const float* __restrict__ x,
             const void* __restrict__ ei,
             const void* __restrict__ batch,
             const float* __restrict__ Wrel1, const float* __restrict__ b1,
             const float* __restrict__ Wroot1,
             const float* __restrict__ Wrel2, const float* __restrict__ b2,
             const float* __restrict__ Wroot2,
             const float* __restrict__ Wrel3, const float* __restrict__ b3,
             const float* __restrict__ Wroot3,
             const float* __restrict__ Wlin, const float* __restrict__ blin,
             float* __restrict__ out, int n, int nE, int ng) {
    __shared__ float sW[2 * HH * HH + HH];
    __shared__ int s_wsum[NTHR / 32];
    __shared__ int s_boff;
    int t = threadIdx.x;
    int gtid = blockIdx.x * NTHR + t;
    int lane = t & 31;
    int wid = t >> 5;

    // dtype detect: int64 ids have zero high words; P(FP) ~ 2^-4096.
    unsigned oddw = 0;
    if (t < 128) oddw = ((const unsigned*)ei)[2 * t + 1];
    bool is64 = (__syncthreads_or(oddw != 0u) == 0);

    // ---- phase 0: zero histogram + half-cast x into g_xh ----
    for (int i = gtid; i < n; i += NT) g_cursor[i] = 0;
    for (int i = gtid; i < n * XH; i += NT) {
        int row = i / XH, col = i % XH;
        g_xh[i] = (col < FF) ? __float2half(x[row * FF + col]) : __half(0.0f);
    }
    grid_sync();

    // ---- phase 1: in-degree histogram over dst ----
    if (is64) {
        const long long* e = (const long long*)ei;
        for (int k = gtid; k < nE; k += NT)
            atomicAdd(&g_cursor[(int)e[nE + k]], 1);
    } else {
        const int* e = (const int*)ei;
        for (int k = gtid; k < nE; k += NT)
            atomicAdd(&g_cursor[e[nE + k]], 1);
    }
    grid_sync();

    // ---- phase 2: per-block exclusive scan of chunk; block sums out ----
    int chunk = (n + NBLK - 1) / NBLK;          // 676 (<= 2*NTHR)
    int base = blockIdx.x * chunk;
    {
        int i0 = 2 * t, i1 = 2 * t + 1;
        int v0 = (i0 < chunk && base + i0 < n) ? g_cursor[base + i0] : 0;
        int v1 = (i1 < chunk && base + i1 < n) ? g_cursor[base + i1] : 0;
        int ts = v0 + v1;
        int sc = ts;
        #pragma unroll
        for (int off = 1; off < 32; off <<= 1) {
            int u = __shfl_up_sync(0xFFFFFFFFu, sc, off);
            if (lane >= off) sc += u;
        }
        if (lane == 31) s_wsum[wid] = sc;
        __syncthreads();
        if (wid == 0) {
            int ws = (lane < NTHR / 32) ? s_wsum[lane] : 0;
            int wsc = ws;
            #pragma unroll
            for (int off = 1; off < 32; off <<= 1) {
                int u = __shfl_up_sync(0xFFFFFFFFu, wsc, off);
                if (lane >= off) wsc += u;
            }
            if (lane < NTHR / 32) s_wsum[lane] = wsc - ws;
            if (lane == NTHR / 32 - 1) g_bsum[blockIdx.x] = wsc;
        }
        __syncthreads();
        int excl = s_wsum[wid] + (sc - ts);
        if (i0 < chunk && base + i0 < n) g_row_ptr[base + i0] = excl;
        if (i1 < chunk && base + i1 < n) g_row_ptr[base + i1] = excl + v0;
    }
    grid_sync();

    // ---- phase 3: parallel block-offset reduce; finalize row_ptr/cursor --
    {
        int v = (t < NBLK && t < (int)blockIdx.x) ? g_bsum[t] : 0;
        #pragma unroll
        for (int off = 16; off > 0; off >>= 1)
            v += __shfl_down_sync(0xFFFFFFFFu, v, off);
        if (lane == 0) s_wsum[wid] = v;
        __syncthreads();
        if (t == 0) {
            int s = 0;
            #pragma unroll
            for (int k = 0; k < NTHR / 32; k++) s += s_wsum[k];
            s_boff = s;
            if (blockIdx.x == 0) g_row_ptr[n] = nE;
        }
        __syncthreads();
        int boff = s_boff;
        for (int i = t; i < chunk; i += NTHR) {
            int gi = base + i;
            if (gi < n) {
                int vv = g_row_ptr[gi] + boff;
                g_row_ptr[gi] = vv;
                g_cursor[gi] = vv;
            }
        }
    }
    grid_sync();

    // ---- phase 4: fill col (CSR by dst, values = src) ----
    if (is64) {
        const long long* e = (const long long*)ei;
        for (int k = gtid; k < nE; k += NT) {
            int s = (int)e[k];
            int d = (int)e[nE + k];
            g_col[atomicAdd(&g_cursor[d], 1)] = s;
        }
    } else {
        const int* e = (const int*)ei;
        for (int k = gtid; k < nE; k += NT) {
            int s = e[k];
            int d = e[nE + k];
            g_col[atomicAdd(&g_cursor[d], 1)] = s;
        }
    }
    grid_sync();

    // ---- layers ----
    layer_phase<FF, XH, true>(g_xh, x, FF, Wrel1, b1, Wroot1,
                              g_h1f, g_h1h, n, sW, gtid);
    grid_sync();
    layer_phase<HH, HHP, true>(g_h1h, g_h1f, HH, Wrel2, b2, Wroot2,
                               g_h2f, g_h2h, n, sW, gtid);
    grid_sync();
    layer_phase<HH, HHP, false>(g_h2h, g_h2f, HH, Wrel3, b3, Wroot3,
                                g_h1f, (__half*)nullptr, n, sW, gtid);
    grid_sync();

    // ---- pool + readout ----
    pool_readout_phase(g_h1f, batch, is64, Wlin, blin, out, n, ng, gtid);
}

// ---------------- launcher: ONE kernel launch ----------------------------
extern "C" void kernel_launch(void* const* d_in, const int* in_sizes, int n_in,
                              void* d_out, int out_size) {
    const float* x      = (const float*)d_in[0];
    const void*  ei     = d_in[1];
    const void*  batch  = d_in[2];
    const float* Wrel1  = (const float*)d_in[3];
    const float* b1     = (const float*)d_in[4];
    const float* Wroot1 = (const float*)d_in[5];
    const float* Wrel2  = (const float*)d_in[6];
    const float* b2     = (const float*)d_in[7];
    const float* Wroot2 = (const float*)d_in[8];
    const float* Wrel3  = (const float*)d_in[9];
    const float* b3     = (const float*)d_in[10];
    const float* Wroot3 = (const float*)d_in[11];
    const float* Wlin   = (const float*)d_in[12];
    const float* blin   = (const float*)d_in[13];

    const int n  = in_sizes[0] / FF;
    const int nE = in_sizes[1] / 2;
    const int ng = out_size / 2;

    fused_kernel<<<NBLK, NTHR>>>(x, ei, batch,
                                 Wrel1, b1, Wroot1,
                                 Wrel2, b2, Wroot2,
                                 Wrel3, b3, Wroot3,
                                 Wlin, blin, (float*)d_out, n, nE, ng);
}